// round 13
// baseline (speedup 1.0000x reference)
#include <cuda_runtime.h>
#include <cuda_bf16.h>
#include <cuda_fp8.h>
#include <cstdint>

// Energy-distance loss, FP8 QMMA f32-acc.
//   loss = mean_b[ mean||x-y|| - 0.5 mean||x-x'|| - 0.5 mean||y-y'|| ]
// R13: occupancy restructure. 512 threads/CTA, 16 warps in 4x4, warp tile
// 32x32 (32 acc regs), 2 CTAs/SM -> 8 warps/SMSP (was 4). Same CTA tile,
// staging, barrier scheme as R12. Diag tiles: wn<wm warps skip (6/16),
// only wn==wm warps run the masked epilogue.

#define NPTS  512
#define DIMS  128
#define NB    128
#define NROWS 65536
#define N_CROSS_CTAS 2048
#define N_SELF_CTAS  1280
#define N_JOBS (N_CROSS_CTAS + 2 * N_SELF_CTAS)   // 4608
#define N_CTAS 296                                 // 2 per SM
// 4608 = 168*16 + 128*15

__device__ uint8_t g_fx[NROWS * DIMS];   // e4m3
__device__ uint8_t g_fy[NROWS * DIMS];
__device__ float g_norm_x[NROWS];
__device__ float g_norm_y[NROWS];
__device__ float g_partials[N_CTAS * 16]; // signed per-warp totals
__device__ unsigned g_done;               // zero-init; reset by last CTA

// smem layout (bytes from 1024-aligned base)
#define OFF_A    0        // 16 KB fp8 tile, 128B rows, xor-swizzled
#define OFF_B    16384
#define OFF_NX   32768
#define OFF_NY   33280
#define SMEM_REQ (1024 + 33792)

__device__ __forceinline__ uint32_t smem_u32(const void* p) {
    uint32_t a;
    asm("{ .reg .u64 t; cvta.to.shared.u64 t, %1; cvt.u32.u64 %0, t; }"
        : "=r"(a) : "l"(p));
    return a;
}

// ---------------------------------------------------------------------------
// Kernel 0: fp32 -> e4m3 convert + exact fp32 squared norms. 8 rows/warp.
// ---------------------------------------------------------------------------
__global__ void prep_kernel(const float* __restrict__ X,
                            const float* __restrict__ Y) {
    int warp = (blockIdx.x * blockDim.x + threadIdx.x) >> 5;
    int lane = threadIdx.x & 31;
    int row8 = warp * 8;
    const float* src; uint8_t* dst; float* ndst; int r0;
    if (row8 < NROWS) { src = X; dst = g_fx; ndst = g_norm_x; r0 = row8; }
    else              { src = Y; dst = g_fy; ndst = g_norm_y; r0 = row8 - NROWS; }

    float4 v[8];
    float s[8];
#pragma unroll
    for (int k = 0; k < 8; k++) {
        v[k] = __ldcs(((const float4*)(src + (size_t)(r0 + k) * DIMS)) + lane);
        s[k] = v[k].x * v[k].x + v[k].y * v[k].y + v[k].z * v[k].z + v[k].w * v[k].w;
    }
#pragma unroll
    for (int k = 0; k < 8; k++) {
        float2 lo = make_float2(v[k].x, v[k].y);
        float2 hi = make_float2(v[k].z, v[k].w);
        unsigned p0 = __nv_cvt_float2_to_fp8x2(lo, __NV_SATFINITE, __NV_E4M3);
        unsigned p1 = __nv_cvt_float2_to_fp8x2(hi, __NV_SATFINITE, __NV_E4M3);
        *(unsigned*)(dst + (size_t)(r0 + k) * DIMS + lane * 4) =
            (p0 & 0xffffu) | (p1 << 16);
#pragma unroll
        for (int o = 16; o; o >>= 1) s[k] += __shfl_xor_sync(0xffffffffu, s[k], o);
        if (lane == 0) ndst[r0 + k] = s[k];
    }
}

// ---------------------------------------------------------------------------
// Kernel 1: 128x128 distance tiles via e4m3 QMMA + fused finalize.
// 512 threads, 16 warps (4m x 4n), warp tile 32x32.
// ---------------------------------------------------------------------------
__global__ __launch_bounds__(512, 2)
void dist_kernel(float* __restrict__ out) {
    extern __shared__ char dyn_smem[];
    char* sm = (char*)((((uintptr_t)dyn_smem) + 1023) & ~(uintptr_t)1023);
    uint32_t sbase = smem_u32(sm);

    int tid  = threadIdx.x;
    int lane = tid & 31;
    int warp = tid >> 5;
    int wm   = warp >> 2;      // 0..3: 32-row band
    int wn   = warp & 3;       // 0..3: 32-col band
    int g    = lane >> 2;
    int ct   = lane & 3;

    // ---- per-thread constants ----
    int a_r = (lane & 7) + ((lane >> 3) & 1) * 8;
    int a_u = lane >> 4;
    int b_r = (lane & 7) + ((lane >> 4) << 3);
    int b_u = (lane >> 3) & 1;

    uint32_t A_base[2], B_base[2];
#pragma unroll
    for (int mt = 0; mt < 2; mt++) {
        int r = wm * 32 + mt * 16 + a_r;
        int s = r & 7;
        A_base[mt] = sbase + OFF_A + r * 128
                   + (((a_u ^ (s & 1)) | (s & 6)) << 4);
    }
#pragma unroll
    for (int pb = 0; pb < 2; pb++) {
        int r = wn * 32 + pb * 16 + b_r;
        int s = r & 7;
        B_base[pb] = sbase + OFF_B + r * 128
                   + (((b_u ^ (s & 1)) | (s & 6)) << 4);
    }

    // staging offsets: 1024 uint4 per matrix, 512 threads -> 2 each
    int st_soff[2], st_goff[2];
#pragma unroll
    for (int q = 0; q < 2; q++) {
        int idx = tid + q * 512;
        int r = idx >> 3, u = idx & 7;
        st_soff[q] = r * 128 + ((u ^ (r & 7)) << 4);
        st_goff[q] = r * DIMS + u * 16;
    }

    int cta = blockIdx.x;
    int j0 = (cta < 168) ? cta * 16 : 168 * 16 + (cta - 168) * 15;
    int j1 = j0 + ((cta < 168) ? 16 : 15);

    const uint8_t* prevAbase = (const uint8_t*)0;
    float tot0 = 0.f, tot1 = 0.f;    // signed, cross jobs

    for (int job = j0; job < j1; job++) {
        // ---- job decode ----
        const uint8_t *Ap, *Bp;
        const float *nAp, *nBp;
        int b, tr, tc;
        bool selfm;
        if (job < N_CROSS_CTAS) {
            b = job >> 4;
            int t = job & 15;
            tr = t >> 2; tc = t & 3;
            Ap = g_fx; Bp = g_fy; nAp = g_norm_x; nBp = g_norm_y;
            selfm = false;
        } else {
            int r = job - N_CROSS_CTAS;
            int isY = (r >= N_SELF_CTAS);
            if (isY) r -= N_SELF_CTAS;
            b = r / 10;
            int t = r - b * 10;
            int trr = 0, tt = t;
            while (tt >= 4 - trr) { tt -= 4 - trr; trr++; }
            tr = trr; tc = trr + tt;
            Ap = isY ? g_fy : g_fx;
            Bp = Ap;
            nAp = isY ? g_norm_y : g_norm_x;
            nBp = nAp;
            selfm = true;
        }
        bool diag = selfm && (tr == tc);
        const uint8_t* Abase = Ap + ((size_t)b * NPTS + tr * 128) * DIMS;
        const uint8_t* Bbase = Bp + ((size_t)b * NPTS + tc * 128) * DIMS;
        bool reuseA = (Abase == prevAbase);
        prevAbase = Abase;

        // ---- stage via cp.async ----
#pragma unroll
        for (int q = 0; q < 2; q++) {
            asm volatile("cp.async.cg.shared.global [%0], [%1], 16;"
                         :: "r"(sbase + OFF_B + st_soff[q]),
                            "l"((const void*)(Bbase + st_goff[q])));
            if (!reuseA)
                asm volatile("cp.async.cg.shared.global [%0], [%1], 16;"
                             :: "r"(sbase + OFF_A + st_soff[q]),
                                "l"((const void*)(Abase + st_goff[q])));
        }
        if (tid < 128) {
            if (!reuseA)
                *(float*)(sm + OFF_NX + tid * 4) = nAp[b * NPTS + tr * 128 + tid];
        } else if (tid < 256) {
            *(float*)(sm + OFF_NY + (tid - 128) * 4) = nBp[b * NPTS + tc * 128 + tid - 128];
        }
        asm volatile("cp.async.commit_group;");
        asm volatile("cp.async.wait_group 0;" ::: "memory");
        __syncthreads();

        // Diag tiles: warp blocks strictly below the diagonal (wn < wm) skip.
        bool skip = diag && (wn < wm);
        if (!skip) {
            // ---- mainloop: 4 k32 chunks ----
            float acc[2][4][4];
#pragma unroll
            for (int mt = 0; mt < 2; mt++)
#pragma unroll
                for (int nt = 0; nt < 4; nt++)
#pragma unroll
                    for (int c = 0; c < 4; c++) acc[mt][nt][c] = 0.f;

#pragma unroll
            for (int kk = 0; kk < 4; kk++) {
                unsigned af[2][4];
#pragma unroll
                for (int mt = 0; mt < 2; mt++) {
                    unsigned addr = A_base[mt] ^ (unsigned)(kk << 5);
                    asm volatile(
                        "ldmatrix.sync.aligned.m8n8.x4.shared.b16 {%0,%1,%2,%3}, [%4];"
                        : "=r"(af[mt][0]), "=r"(af[mt][1]), "=r"(af[mt][2]), "=r"(af[mt][3])
                        : "r"(addr));
                }
#pragma unroll
                for (int pb = 0; pb < 2; pb++) {
                    unsigned addr = B_base[pb] ^ (unsigned)(kk << 5);
                    unsigned bf[4];
                    asm volatile(
                        "ldmatrix.sync.aligned.m8n8.x4.shared.b16 {%0,%1,%2,%3}, [%4];"
                        : "=r"(bf[0]), "=r"(bf[1]), "=r"(bf[2]), "=r"(bf[3])
                        : "r"(addr));
#pragma unroll
                    for (int mt = 0; mt < 2; mt++) {
                        asm volatile(
                            "mma.sync.aligned.m16n8k32.row.col.f32.e4m3.e4m3.f32 "
                            "{%0,%1,%2,%3}, {%4,%5,%6,%7}, {%8,%9}, {%0,%1,%2,%3};"
                            : "+f"(acc[mt][2*pb][0]), "+f"(acc[mt][2*pb][1]),
                              "+f"(acc[mt][2*pb][2]), "+f"(acc[mt][2*pb][3])
                            : "r"(af[mt][0]), "r"(af[mt][1]), "r"(af[mt][2]), "r"(af[mt][3]),
                              "r"(bf[0]), "r"(bf[1]));
                        asm volatile(
                            "mma.sync.aligned.m16n8k32.row.col.f32.e4m3.e4m3.f32 "
                            "{%0,%1,%2,%3}, {%4,%5,%6,%7}, {%8,%9}, {%0,%1,%2,%3};"
                            : "+f"(acc[mt][2*pb+1][0]), "+f"(acc[mt][2*pb+1][1]),
                              "+f"(acc[mt][2*pb+1][2]), "+f"(acc[mt][2*pb+1][3])
                            : "r"(af[mt][0]), "r"(af[mt][1]), "r"(af[mt][2]), "r"(af[mt][3]),
                              "r"(bf[2]), "r"(bf[3]));
                    }
                }
            }

            // ---- epilogue ----
            float nx[2][2];
#pragma unroll
            for (int mt = 0; mt < 2; mt++) {
                int r0 = wm * 32 + mt * 16 + g;
                nx[mt][0] = *(const float*)(sm + OFF_NX + r0 * 4);
                nx[mt][1] = *(const float*)(sm + OFF_NX + (r0 + 8) * 4);
            }
            float ny[4][2];
#pragma unroll
            for (int nt = 0; nt < 4; nt++) {
                int c0 = wn * 32 + nt * 8 + 2 * ct;
                ny[nt][0] = *(const float*)(sm + OFF_NY + c0 * 4);
                ny[nt][1] = *(const float*)(sm + OFF_NY + (c0 + 1) * 4);
            }

            float ts0 = 0.f, ts1 = 0.f;
            if (diag && (wn == wm)) {
                // straddles the diagonal: masked epilogue
#pragma unroll
                for (int mt = 0; mt < 2; mt++)
#pragma unroll
                    for (int nt = 0; nt < 4; nt++)
#pragma unroll
                        for (int c = 0; c < 4; c++) {
                            int ri = c >> 1, cj = c & 1;
                            int irow = mt * 16 + g + ri * 8;            // within band
                            int jcol = nt * 8 + 2 * ct + cj;            // within band
                            float d2 = fmaf(acc[mt][nt][c], -2.f, nx[mt][ri]) + ny[nt][cj];
                            float dd;
                            asm("sqrt.approx.f32 %0, %1;" : "=f"(dd) : "f"(d2));
                            if (jcol <= irow) dd = 0.f;   // also kills NaN at i==j
                            if (c & 1) ts1 += dd; else ts0 += dd;
                        }
            } else {
#pragma unroll
                for (int mt = 0; mt < 2; mt++)
#pragma unroll
                    for (int nt = 0; nt < 4; nt++)
#pragma unroll
                        for (int c = 0; c < 4; c++) {
                            float d2 = fmaf(acc[mt][nt][c], -2.f, nx[mt][c >> 1]) + ny[nt][c & 1];
                            float dd;
                            asm("sqrt.approx.f32 %0, %1;" : "=f"(dd) : "f"(d2));
                            if (c & 1) ts1 += dd; else ts0 += dd;
                        }
            }
            if (selfm) { tot0 -= ts0; tot1 -= ts1; }
            else       { tot0 += ts0; tot1 += ts1; }
        }

        __syncthreads();     // licenses smem overwrite by next job
    }

    // ---- single per-warp reduction + write ----
    float tsum = tot0 + tot1;
#pragma unroll
    for (int o = 16; o; o >>= 1) tsum += __shfl_xor_sync(0xffffffffu, tsum, o);
    if (lane == 0) g_partials[cta * 16 + warp] = tsum;

    // ---- fused finalize: last CTA reduces all signed partials ----
    __threadfence();
    __shared__ unsigned s_last;
    if (tid == 0) {
        unsigned ticket = atomicAdd(&g_done, 1u);
        s_last = (ticket == N_CTAS - 1) ? 1u : 0u;
    }
    __syncthreads();
    if (s_last) {
        __threadfence();
        __shared__ double sd[512];
        double s = 0.0;
        for (int i = tid; i < N_CTAS * 16; i += 512)
            s += (double)g_partials[i];
        sd[tid] = s;
        __syncthreads();
        for (int o = 256; o; o >>= 1) {
            if (tid < o) sd[tid] += sd[tid + o];
            __syncthreads();
        }
        if (tid == 0) {
            out[0] = (float)(sd[0] / ((double)NB * NPTS * NPTS));
            g_done = 0;     // reset for next graph replay
        }
    }
}

// ---------------------------------------------------------------------------
extern "C" void kernel_launch(void* const* d_in, const int* in_sizes, int n_in,
                              void* d_out, int out_size) {
    const float* X = (const float*)d_in[0];
    const float* Y = (const float*)d_in[1];

    cudaFuncSetAttribute(dist_kernel,
                         cudaFuncAttributeMaxDynamicSharedMemorySize, SMEM_REQ);

    prep_kernel<<<2048, 256>>>(X, Y);
    dist_kernel<<<N_CTAS, 512, SMEM_REQ>>>((float*)d_out);
}

// round 15
// speedup vs baseline: 1.3624x; 1.3624x over previous
#include <cuda_runtime.h>
#include <cuda_bf16.h>
#include <cuda_fp16.h>
#include <cuda_fp8.h>
#include <cstdint>

// Energy-distance loss, FP8 QMMA f32-acc.
//   loss = mean_b[ mean||x-y|| - 0.5 mean||x-x'|| - 0.5 mean||y-y'|| ]
// R15 = R14 with the f16x2 rsqrt spelled correctly: h2rsqrt() intrinsic
// (lowers to MUFU.RSQ64H; raw "rsqrt.approx.f16x2" PTX does not exist).
// Epilogue is ~276 of ~330 issue slots/warp-job and MUFU ~86% of SFU pipe;
// half2 fast path halves both. Diag-straddling warps keep exact scalar path.

#define NPTS  512
#define DIMS  128
#define NB    128
#define NROWS 65536
#define N_CROSS_CTAS 2048
#define N_SELF_CTAS  1280
#define N_JOBS (N_CROSS_CTAS + 2 * N_SELF_CTAS)   // 4608
#define N_CTAS 296                                 // 2 per SM
// 4608 = 168*16 + 128*15

__device__ uint8_t g_fx[NROWS * DIMS];   // e4m3
__device__ uint8_t g_fy[NROWS * DIMS];
__device__ float g_norm_x[NROWS];
__device__ float g_norm_y[NROWS];
__device__ float g_partials[N_CTAS * 8]; // signed per-warp totals
__device__ unsigned g_done;              // zero-init; reset by last CTA

// smem layout (bytes from 1024-aligned base)
#define OFF_A    0        // 16 KB fp8 tile, 128B rows, xor-swizzled
#define OFF_B    16384
#define OFF_NX   32768
#define OFF_NY   33280
#define SMEM_REQ (1024 + 33792)

__device__ __forceinline__ uint32_t smem_u32(const void* p) {
    uint32_t a;
    asm("{ .reg .u64 t; cvta.to.shared.u64 t, %1; cvt.u32.u64 %0, t; }"
        : "=r"(a) : "l"(p));
    return a;
}

__device__ __forceinline__ unsigned cvt_h2(float lo, float hi) {
    unsigned r;
    asm("cvt.rn.f16x2.f32 %0, %1, %2;" : "=r"(r) : "f"(hi), "f"(lo));
    return r;
}

// ---------------------------------------------------------------------------
// Kernel 0: fp32 -> e4m3 convert + exact fp32 squared norms. 8 rows/warp.
// ---------------------------------------------------------------------------
__global__ void prep_kernel(const float* __restrict__ X,
                            const float* __restrict__ Y) {
    int warp = (blockIdx.x * blockDim.x + threadIdx.x) >> 5;
    int lane = threadIdx.x & 31;
    int row8 = warp * 8;
    const float* src; uint8_t* dst; float* ndst; int r0;
    if (row8 < NROWS) { src = X; dst = g_fx; ndst = g_norm_x; r0 = row8; }
    else              { src = Y; dst = g_fy; ndst = g_norm_y; r0 = row8 - NROWS; }

    float4 v[8];
    float s[8];
#pragma unroll
    for (int k = 0; k < 8; k++) {
        v[k] = __ldcs(((const float4*)(src + (size_t)(r0 + k) * DIMS)) + lane);
        s[k] = v[k].x * v[k].x + v[k].y * v[k].y + v[k].z * v[k].z + v[k].w * v[k].w;
    }
#pragma unroll
    for (int k = 0; k < 8; k++) {
        float2 lo = make_float2(v[k].x, v[k].y);
        float2 hi = make_float2(v[k].z, v[k].w);
        unsigned p0 = __nv_cvt_float2_to_fp8x2(lo, __NV_SATFINITE, __NV_E4M3);
        unsigned p1 = __nv_cvt_float2_to_fp8x2(hi, __NV_SATFINITE, __NV_E4M3);
        *(unsigned*)(dst + (size_t)(r0 + k) * DIMS + lane * 4) =
            (p0 & 0xffffu) | (p1 << 16);
#pragma unroll
        for (int o = 16; o; o >>= 1) s[k] += __shfl_xor_sync(0xffffffffu, s[k], o);
        if (lane == 0) ndst[r0 + k] = s[k];
    }
}

// ---------------------------------------------------------------------------
// Kernel 1: 128x128 distance tiles via e4m3 QMMA + fused finalize.
// ---------------------------------------------------------------------------
__global__ __launch_bounds__(256, 2)
void dist_kernel(float* __restrict__ out) {
    extern __shared__ char dyn_smem[];
    char* sm = (char*)((((uintptr_t)dyn_smem) + 1023) & ~(uintptr_t)1023);
    uint32_t sbase = smem_u32(sm);

    int tid  = threadIdx.x;
    int lane = tid & 31;
    int warp = tid >> 5;
    int wm   = warp >> 1;
    int wn   = warp & 1;
    int g    = lane >> 2;
    int ct   = lane & 3;

    // ---- per-thread constants ----
    int a_r = (lane & 7) + ((lane >> 3) & 1) * 8;
    int a_u = lane >> 4;
    int b_r = (lane & 7) + ((lane >> 4) << 3);
    int b_u = (lane >> 3) & 1;

    uint32_t A_base[2], B_base[4];
#pragma unroll
    for (int mt = 0; mt < 2; mt++) {
        int r = wm * 32 + mt * 16 + a_r;
        int s = r & 7;
        A_base[mt] = sbase + OFF_A + r * 128
                   + (((a_u ^ (s & 1)) | (s & 6)) << 4);
    }
#pragma unroll
    for (int pp = 0; pp < 4; pp++) {
        int r = wn * 64 + pp * 16 + b_r;
        int s = r & 7;
        B_base[pp] = sbase + OFF_B + r * 128
                   + (((b_u ^ (s & 1)) | (s & 6)) << 4);
    }

    int st_soff[4], st_goff[4];
#pragma unroll
    for (int q = 0; q < 4; q++) {
        int idx = tid + q * 256;
        int r = idx >> 3, u = idx & 7;
        st_soff[q] = r * 128 + ((u ^ (r & 7)) << 4);
        st_goff[q] = r * DIMS + u * 16;
    }

    int cta = blockIdx.x;
    int j0 = (cta < 168) ? cta * 16 : 168 * 16 + (cta - 168) * 15;
    int j1 = j0 + ((cta < 168) ? 16 : 15);

    const uint8_t* prevAbase = (const uint8_t*)0;
    float tot0 = 0.f, tot1 = 0.f;    // signed, cross jobs
    const __half2 neg2 = __floats2half2_rn(-2.f, -2.f);

    for (int job = j0; job < j1; job++) {
        // ---- job decode ----
        const uint8_t *Ap, *Bp;
        const float *nAp, *nBp;
        int b, tr, tc;
        bool selfm;
        if (job < N_CROSS_CTAS) {
            b = job >> 4;
            int t = job & 15;
            tr = t >> 2; tc = t & 3;
            Ap = g_fx; Bp = g_fy; nAp = g_norm_x; nBp = g_norm_y;
            selfm = false;
        } else {
            int r = job - N_CROSS_CTAS;
            int isY = (r >= N_SELF_CTAS);
            if (isY) r -= N_SELF_CTAS;
            b = r / 10;
            int t = r - b * 10;
            int trr = 0, tt = t;
            while (tt >= 4 - trr) { tt -= 4 - trr; trr++; }
            tr = trr; tc = trr + tt;
            Ap = isY ? g_fy : g_fx;
            Bp = Ap;
            nAp = isY ? g_norm_y : g_norm_x;
            nBp = nAp;
            selfm = true;
        }
        bool diag = selfm && (tr == tc);
        const uint8_t* Abase = Ap + ((size_t)b * NPTS + tr * 128) * DIMS;
        const uint8_t* Bbase = Bp + ((size_t)b * NPTS + tc * 128) * DIMS;
        bool reuseA = (Abase == prevAbase);
        prevAbase = Abase;

        // ---- stage via cp.async ----
#pragma unroll
        for (int q = 0; q < 4; q++) {
            asm volatile("cp.async.cg.shared.global [%0], [%1], 16;"
                         :: "r"(sbase + OFF_B + st_soff[q]),
                            "l"((const void*)(Bbase + st_goff[q])));
            if (!reuseA)
                asm volatile("cp.async.cg.shared.global [%0], [%1], 16;"
                             :: "r"(sbase + OFF_A + st_soff[q]),
                                "l"((const void*)(Abase + st_goff[q])));
        }
        if (tid < 128) {
            if (!reuseA)
                *(float*)(sm + OFF_NX + tid * 4) = nAp[b * NPTS + tr * 128 + tid];
        } else {
            *(float*)(sm + OFF_NY + (tid - 128) * 4) = nBp[b * NPTS + tc * 128 + tid - 128];
        }
        asm volatile("cp.async.commit_group;");
        asm volatile("cp.async.wait_group 0;" ::: "memory");
        __syncthreads();

        // Diag tiles: warp blocks strictly below the diagonal skip.
        bool skip = diag && (wn == 0) && (wm >= 2);
        if (!skip) {
            // ---- mainloop: 4 k32 chunks, f32 accumulators ----
            float acc[2][8][4];
#pragma unroll
            for (int mt = 0; mt < 2; mt++)
#pragma unroll
                for (int nt = 0; nt < 8; nt++)
#pragma unroll
                    for (int c = 0; c < 4; c++) acc[mt][nt][c] = 0.f;

#pragma unroll
            for (int kk = 0; kk < 4; kk++) {
                unsigned af[2][4];
#pragma unroll
                for (int mt = 0; mt < 2; mt++) {
                    unsigned addr = A_base[mt] ^ (unsigned)(kk << 5);
                    asm volatile(
                        "ldmatrix.sync.aligned.m8n8.x4.shared.b16 {%0,%1,%2,%3}, [%4];"
                        : "=r"(af[mt][0]), "=r"(af[mt][1]), "=r"(af[mt][2]), "=r"(af[mt][3])
                        : "r"(addr));
                }
#pragma unroll
                for (int pp = 0; pp < 4; pp++) {
                    unsigned addr = B_base[pp] ^ (unsigned)(kk << 5);
                    unsigned bf[4];
                    asm volatile(
                        "ldmatrix.sync.aligned.m8n8.x4.shared.b16 {%0,%1,%2,%3}, [%4];"
                        : "=r"(bf[0]), "=r"(bf[1]), "=r"(bf[2]), "=r"(bf[3])
                        : "r"(addr));
#pragma unroll
                    for (int mt = 0; mt < 2; mt++) {
                        asm volatile(
                            "mma.sync.aligned.m16n8k32.row.col.f32.e4m3.e4m3.f32 "
                            "{%0,%1,%2,%3}, {%4,%5,%6,%7}, {%8,%9}, {%0,%1,%2,%3};"
                            : "+f"(acc[mt][2*pp][0]), "+f"(acc[mt][2*pp][1]),
                              "+f"(acc[mt][2*pp][2]), "+f"(acc[mt][2*pp][3])
                            : "r"(af[mt][0]), "r"(af[mt][1]), "r"(af[mt][2]), "r"(af[mt][3]),
                              "r"(bf[0]), "r"(bf[1]));
                        asm volatile(
                            "mma.sync.aligned.m16n8k32.row.col.f32.e4m3.e4m3.f32 "
                            "{%0,%1,%2,%3}, {%4,%5,%6,%7}, {%8,%9}, {%0,%1,%2,%3};"
                            : "+f"(acc[mt][2*pp+1][0]), "+f"(acc[mt][2*pp+1][1]),
                              "+f"(acc[mt][2*pp+1][2]), "+f"(acc[mt][2*pp+1][3])
                            : "r"(af[mt][0]), "r"(af[mt][1]), "r"(af[mt][2]), "r"(af[mt][3]),
                              "r"(bf[2]), "r"(bf[3]));
                    }
                }
            }

            // straddle = warp block contains diagonal elements (only on diag jobs)
            bool straddle = diag && (wm >> 1) == wn;
            if (straddle) {
                // ---- exact scalar masked epilogue (~5% of warp-jobs) ----
                float nx[2][2];
#pragma unroll
                for (int mt = 0; mt < 2; mt++) {
                    int r0 = wm * 32 + mt * 16 + g;
                    nx[mt][0] = *(const float*)(sm + OFF_NX + r0 * 4);
                    nx[mt][1] = *(const float*)(sm + OFF_NX + (r0 + 8) * 4);
                }
                float ny[8][2];
#pragma unroll
                for (int nt = 0; nt < 8; nt++) {
                    int c0 = wn * 64 + nt * 8 + 2 * ct;
                    ny[nt][0] = *(const float*)(sm + OFF_NY + c0 * 4);
                    ny[nt][1] = *(const float*)(sm + OFF_NY + (c0 + 1) * 4);
                }
                float ts0 = 0.f, ts1 = 0.f;
#pragma unroll
                for (int mt = 0; mt < 2; mt++)
#pragma unroll
                    for (int nt = 0; nt < 8; nt++)
#pragma unroll
                        for (int c = 0; c < 4; c++) {
                            int ri = c >> 1, cj = c & 1;
                            int irow = wm * 32 + mt * 16 + g + ri * 8;
                            int jcol = wn * 64 + nt * 8 + 2 * ct + cj;
                            float d2 = fmaf(acc[mt][nt][c], -2.f, nx[mt][ri]) + ny[nt][cj];
                            float dd;
                            asm("sqrt.approx.f32 %0, %1;" : "=f"(dd) : "f"(d2));
                            if (jcol <= irow) dd = 0.f;   // also kills NaN at i==j
                            if (c & 1) ts1 += dd; else ts0 += dd;
                        }
                tot0 -= ts0; tot1 -= ts1;      // straddle only occurs on self
            } else {
                // ---- half2 fast-path epilogue ----
                unsigned nx2[2][2];
#pragma unroll
                for (int mt = 0; mt < 2; mt++) {
                    int r0 = wm * 32 + mt * 16 + g;
                    float n0 = *(const float*)(sm + OFF_NX + r0 * 4);
                    float n1 = *(const float*)(sm + OFF_NX + (r0 + 8) * 4);
                    nx2[mt][0] = cvt_h2(n0, n0);
                    nx2[mt][1] = cvt_h2(n1, n1);
                }
                unsigned ny2[8];
#pragma unroll
                for (int nt = 0; nt < 8; nt++) {
                    float2 v = *(const float2*)(sm + OFF_NY + (wn * 64 + nt * 8 + 2 * ct) * 4);
                    ny2[nt] = cvt_h2(v.x, v.y);
                }

                __half2 ch0 = __floats2half2_rn(0.f, 0.f);
                __half2 ch1 = ch0, ch2 = ch0, ch3 = ch0;
#pragma unroll
                for (int mt = 0; mt < 2; mt++)
#pragma unroll
                    for (int nt = 0; nt < 8; nt++)
#pragma unroll
                        for (int ri = 0; ri < 2; ri++) {
                            unsigned a2u = cvt_h2(acc[mt][nt][2 * ri],
                                                  acc[mt][nt][2 * ri + 1]);
                            __half2 s2 = __hadd2(*(__half2*)&nx2[mt][ri],
                                                 *(__half2*)&ny2[nt]);
                            __half2 d2 = __hfma2(*(__half2*)&a2u, neg2, s2);
                            __half2 r2 = h2rsqrt(d2);          // MUFU.RSQ64H
                            __half2 dh = __hmul2(d2, r2);
                            int chain = mt * 2 + ri;
                            if      (chain == 0) ch0 = __hadd2(ch0, dh);
                            else if (chain == 1) ch1 = __hadd2(ch1, dh);
                            else if (chain == 2) ch2 = __hadd2(ch2, dh);
                            else                 ch3 = __hadd2(ch3, dh);
                        }
                float2 f0 = __half22float2(ch0);
                float2 f1 = __half22float2(ch1);
                float2 f2 = __half22float2(ch2);
                float2 f3 = __half22float2(ch3);
                float ts0 = (f0.x + f1.x) + (f2.x + f3.x);
                float ts1 = (f0.y + f1.y) + (f2.y + f3.y);
                if (selfm) { tot0 -= ts0; tot1 -= ts1; }
                else       { tot0 += ts0; tot1 += ts1; }
            }
        }

        __syncthreads();     // licenses smem overwrite by next job
    }

    // ---- single per-warp reduction + write ----
    float tsum = tot0 + tot1;
#pragma unroll
    for (int o = 16; o; o >>= 1) tsum += __shfl_xor_sync(0xffffffffu, tsum, o);
    if (lane == 0) g_partials[cta * 8 + warp] = tsum;

    // ---- fused finalize: last CTA reduces all signed partials ----
    __threadfence();
    __shared__ unsigned s_last;
    if (tid == 0) {
        unsigned ticket = atomicAdd(&g_done, 1u);
        s_last = (ticket == N_CTAS - 1) ? 1u : 0u;
    }
    __syncthreads();
    if (s_last) {
        __threadfence();
        __shared__ double sd[256];
        double s = 0.0;
        for (int i = tid; i < N_CTAS * 8; i += 256)
            s += (double)g_partials[i];
        sd[tid] = s;
        __syncthreads();
        for (int o = 128; o; o >>= 1) {
            if (tid < o) sd[tid] += sd[tid + o];
            __syncthreads();
        }
        if (tid == 0) {
            out[0] = (float)(sd[0] / ((double)NB * NPTS * NPTS));
            g_done = 0;     // reset for next graph replay
        }
    }
}

// ---------------------------------------------------------------------------
extern "C" void kernel_launch(void* const* d_in, const int* in_sizes, int n_in,
                              void* d_out, int out_size) {
    const float* X = (const float*)d_in[0];
    const float* Y = (const float*)d_in[1];

    cudaFuncSetAttribute(dist_kernel,
                         cudaFuncAttributeMaxDynamicSharedMemorySize, SMEM_REQ);

    prep_kernel<<<2048, 256>>>(X, Y);
    dist_kernel<<<N_CTAS, 256, SMEM_REQ>>>((float*)d_out);
}